// round 6
// baseline (speedup 1.0000x reference)
#include <cuda_runtime.h>

#define NN 100000
#define EE 3200000

// ---------------- scratch (device globals; never passed as kernel args) ----
__device__ __align__(16) int   g_cnt[NN];        // histogram, then scatter cursor
__device__ __align__(16) float g_dis[NN];        // weighted degree, then deg^-1/2
__device__ __align__(16) int   g_off[NN + 1];    // CSR offsets (by col)
__device__ __align__(16) int   g_bsum[128];
__device__ __align__(16) int   g_bsum2[128];
__device__ __align__(16) int2  g_csr[EE];        // (row, norm-as-int) grouped by col
__device__ __align__(16) float g_A[NN * 48];     // conv1 state ping
__device__ __align__(16) float g_B[NN * 48];     // conv1 state pong
__device__ __align__(16) float g_Z2a[NN * 4];    // conv2 ping (K=3 padded to 4)
__device__ __align__(16) float g_Z2b[NN * 4];    // conv2 pong
__device__ __align__(16) float g_root2[NN * 4];

// ---------------- CSR build ------------------------------------------------
__global__ void __launch_bounds__(256) k_zero() {
    int n = blockIdx.x * blockDim.x + threadIdx.x;
    if (n < NN) { g_cnt[n] = 0; g_dis[n] = 0.f; }
}

__global__ void __launch_bounds__(256) k_hist(const int* __restrict__ col,
                                              const float* __restrict__ ew) {
    int e = blockIdx.x * blockDim.x + threadIdx.x;
    if (e >= EE) return;
    int c = col[e];
    atomicAdd(&g_cnt[c], 1);
    atomicAdd(&g_dis[c], ew[e]);
}

__global__ void __launch_bounds__(256) k_dis() {
    int n = blockIdx.x * blockDim.x + threadIdx.x;
    if (n >= NN) return;
    float d = g_dis[n];
    g_dis[n] = (d > 0.f) ? rsqrtf(fmaxf(d, 1e-12f)) : 0.f;
}

__global__ void __launch_bounds__(1024) k_scan1() {
    __shared__ int s[1024];
    int i = blockIdx.x * 1024 + threadIdx.x;
    int v = (i < NN) ? g_cnt[i] : 0;
    s[threadIdx.x] = v;
    __syncthreads();
#pragma unroll
    for (int off = 1; off < 1024; off <<= 1) {
        int t = (threadIdx.x >= off) ? s[threadIdx.x - off] : 0;
        __syncthreads();
        s[threadIdx.x] += t;
        __syncthreads();
    }
    if (i < NN) g_off[i] = s[threadIdx.x] - v;
    if (threadIdx.x == 1023) g_bsum[blockIdx.x] = s[1023];
}

__global__ void __launch_bounds__(32) k_scan2(int nb) {
    if (threadIdx.x == 0 && blockIdx.x == 0) {
        int acc = 0;
        for (int b = 0; b < nb; b++) { g_bsum2[b] = acc; acc += g_bsum[b]; }
    }
}

__global__ void __launch_bounds__(256) k_scan3() {
    int i = blockIdx.x * blockDim.x + threadIdx.x;
    if (i < NN) {
        int v = g_off[i] + g_bsum2[i >> 10];
        g_off[i] = v;
        g_cnt[i] = v;
    }
    if (i == 0) g_off[NN] = EE;
}

__global__ void __launch_bounds__(256) k_scatter(const int* __restrict__ row,
                                                 const int* __restrict__ col,
                                                 const float* __restrict__ ew) {
    int e = blockIdx.x * blockDim.x + threadIdx.x;
    if (e >= EE) return;
    int r = row[e], c = col[e];
    float nm = g_dis[r] * ew[e] * g_dis[c];
    int p = atomicAdd(&g_cnt[c], 1);
    g_csr[p] = make_int2(r, __float_as_int(nm));
}

// ---------------- conv1 first iteration (rank-1): warp per node ------------
// s1 = (Lx)[n]; out_1 = relu(s1*iw + x*rw + b) -> g_A
__global__ void __launch_bounds__(256) k_first(const float* __restrict__ x,
                                               const float* __restrict__ iw,
                                               const float* __restrict__ rw,
                                               const float* __restrict__ bias) {
    __shared__ float siw[48], srw[48], sb[48];
    if (threadIdx.x < 48) {
        siw[threadIdx.x] = iw[threadIdx.x];
        srw[threadIdx.x] = rw[threadIdx.x];
        sb[threadIdx.x]  = bias[threadIdx.x];
    }
    __syncthreads();
    int n = blockIdx.x * 8 + (threadIdx.x >> 5);   // 12500*8 = 100000 exact
    int lane = threadIdx.x & 31;
    int beg = g_off[n], end = g_off[n + 1];
    float acc = 0.f;
    for (int p = beg + lane; p < end; p += 32) {
        int2 ent = __ldg(&g_csr[p]);
        acc += __int_as_float(ent.y) * __ldg(x + ent.x);
    }
#pragma unroll
    for (int o = 16; o; o >>= 1) acc += __shfl_xor_sync(0xffffffffu, acc, o);
    float s1 = __shfl_sync(0xffffffffu, acc, 0);
    if (lane < 12) {
        float s0 = __ldg(x + n);
        int i = lane * 4;
        float4 a;
        a.x = fmaxf(s1 * siw[i+0] + s0 * srw[i+0] + sb[i+0], 0.f);
        a.y = fmaxf(s1 * siw[i+1] + s0 * srw[i+1] + sb[i+1], 0.f);
        a.z = fmaxf(s1 * siw[i+2] + s0 * srw[i+2] + sb[i+2], 0.f);
        a.w = fmaxf(s1 * siw[i+3] + s0 * srw[i+3] + sb[i+3], 0.f);
        *(float4*)(g_A + (size_t)n * 48 + i) = a;
    }
}

// ---------------- conv1 fused gather + node update -------------------------
// 12-thread groups, 32 nodes per 384-thread block (exact: 3125*32 = 100000).
// STEP 0: B = relu((L A)@W + x*rw + b)
// STEP 1: A = relu((L B)@W + x*rw + b)
// STEP 2: full tail -> g_Z2a (conv2 init), g_root2
template <int STEP>
__global__ void __launch_bounds__(384) k_gath_fused(
    const float* __restrict__ x, const float* __restrict__ W,
    const float* __restrict__ rw, const float* __restrict__ bias,
    const float* __restrict__ gamma, const float* __restrict__ beta,
    const float* __restrict__ mean, const float* __restrict__ var,
    const float* __restrict__ iw2, const float* __restrict__ rw2,
    const float* __restrict__ b2) {
    const float* src = (STEP == 1) ? g_B : g_A;
    float* dst = (STEP == 0) ? g_B : g_A;   // unused in STEP 2

    __shared__ float sW[768], srw[48], sb[48];
    __shared__ float so[32][52];
    __shared__ float so2[32][48];           // STEP 2 only
    __shared__ float sscale[16], sshift[16], siw2[48], srw2[48], sb2[4];
    for (int i = threadIdx.x; i < 768; i += 384) sW[i] = W[i];
    if (threadIdx.x < 48) {
        srw[threadIdx.x] = rw[threadIdx.x];
        sb[threadIdx.x]  = bias[threadIdx.x];
    }
    if (STEP == 2) {
        if (threadIdx.x >= 64 && threadIdx.x < 80) {
            int f = threadIdx.x - 64;
            float sc = gamma[f] * rsqrtf(var[f] + 1e-5f);
            sscale[f] = sc;
            sshift[f] = beta[f] - mean[f] * sc;
        }
        if (threadIdx.x >= 96 && threadIdx.x < 144) {
            siw2[threadIdx.x - 96] = iw2[threadIdx.x - 96];
            srw2[threadIdx.x - 96] = rw2[threadIdx.x - 96];
        }
        if (threadIdx.x >= 160 && threadIdx.x < 163) sb2[threadIdx.x - 160] = b2[threadIdx.x - 160];
    }
    __syncthreads();

    int gid = threadIdx.x / 12;            // 0..31 (384 = 32*12 exact)
    int l = threadIdx.x - gid * 12;        // 0..11
    int l4 = l * 4;
    int n = blockIdx.x * 32 + gid;         // always < NN

    int beg = g_off[n], end = g_off[n + 1];
    float4 acc = make_float4(0.f, 0.f, 0.f, 0.f);
    int p = beg;
    for (; p + 4 <= end; p += 4) {         // MLP-4 unroll
        int2 e0 = __ldg(&g_csr[p + 0]);
        int2 e1 = __ldg(&g_csr[p + 1]);
        int2 e2 = __ldg(&g_csr[p + 2]);
        int2 e3 = __ldg(&g_csr[p + 3]);
        float4 v0 = *(const float4*)(src + (size_t)e0.x * 48 + l4);
        float4 v1 = *(const float4*)(src + (size_t)e1.x * 48 + l4);
        float4 v2 = *(const float4*)(src + (size_t)e2.x * 48 + l4);
        float4 v3 = *(const float4*)(src + (size_t)e3.x * 48 + l4);
        float w0 = __int_as_float(e0.y), w1 = __int_as_float(e1.y);
        float w2 = __int_as_float(e2.y), w3 = __int_as_float(e3.y);
        acc.x += w0 * v0.x; acc.y += w0 * v0.y; acc.z += w0 * v0.z; acc.w += w0 * v0.w;
        acc.x += w1 * v1.x; acc.y += w1 * v1.y; acc.z += w1 * v1.z; acc.w += w1 * v1.w;
        acc.x += w2 * v2.x; acc.y += w2 * v2.y; acc.z += w2 * v2.z; acc.w += w2 * v2.w;
        acc.x += w3 * v3.x; acc.y += w3 * v3.y; acc.z += w3 * v3.z; acc.w += w3 * v3.w;
    }
    for (; p < end; ++p) {
        int2 ent = __ldg(&g_csr[p]);
        float w = __int_as_float(ent.y);
        float4 v = *(const float4*)(src + (size_t)ent.x * 48 + l4);
        acc.x += w * v.x; acc.y += w * v.y; acc.z += w * v.z; acc.w += w * v.w;
    }
    so[gid][l4 + 0] = acc.x;
    so[gid][l4 + 1] = acc.y;
    so[gid][l4 + 2] = acc.z;
    so[gid][l4 + 3] = acc.w;
    __syncthreads();

    // o = relu(Y@W + x*rw + b); thread computes outputs [k*16+p4 .. +3]
    float xv = __ldg(x + n);
    int k = l >> 2, p4 = (l & 3) * 4;
    const float* yk = &so[gid][k * 16];
    float4 o;
    o.x = xv * srw[k * 16 + p4 + 0] + sb[k * 16 + p4 + 0];
    o.y = xv * srw[k * 16 + p4 + 1] + sb[k * 16 + p4 + 1];
    o.z = xv * srw[k * 16 + p4 + 2] + sb[k * 16 + p4 + 2];
    o.w = xv * srw[k * 16 + p4 + 3] + sb[k * 16 + p4 + 3];
#pragma unroll
    for (int q = 0; q < 16; q++) {
        float yv = yk[q];
        const float* wq = &sW[k * 256 + q * 16 + p4];
        o.x += yv * wq[0];
        o.y += yv * wq[1];
        o.z += yv * wq[2];
        o.w += yv * wq[3];
    }
    o.x = fmaxf(o.x, 0.f); o.y = fmaxf(o.y, 0.f);
    o.z = fmaxf(o.z, 0.f); o.w = fmaxf(o.w, 0.f);

    if (STEP != 2) {
        *(float4*)(dst + (size_t)n * 48 + l4) = o;
        return;
    }

    // STEP 2 tail: mean over K, BN, ReLU, conv2 init
    so2[gid][l4 + 0] = o.x;
    so2[gid][l4 + 1] = o.y;
    so2[gid][l4 + 2] = o.z;
    so2[gid][l4 + 3] = o.w;
    __syncthreads();
    if (l >= 3) return;
    int kk = l;  // one thread per stack
    float za = 0.f, ra = 0.f;
#pragma unroll
    for (int f = 0; f < 16; f++) {
        float h = (so2[gid][f] + so2[gid][16 + f] + so2[gid][32 + f]) * (1.f / 3.f);
        h = fmaxf(h * sscale[f] + sshift[f], 0.f);
        za += h * siw2[kk * 16 + f];
        ra += h * srw2[kk * 16 + f];
    }
    g_Z2a[(size_t)n * 4 + kk]   = za;
    g_root2[(size_t)n * 4 + kk] = ra + sb2[kk];
    if (kk == 0) {
        g_Z2a[(size_t)n * 4 + 3]   = 0.f;
        g_root2[(size_t)n * 4 + 3] = 0.f;
    }
}

// ---------------- conv2 gather + fused node update -------------------------
// STEP 0: Z2b = L Z2a + root2
// STEP 1: Z2a = w * (L Z2b) + root2
// STEP 2: Z2b = w * (L Z2a) + root2
// STEP 3: out = sigmoid(mean(w * (L Z2b) + root2))
template <int STEP>
__global__ void __launch_bounds__(256) k_gath4(const float* __restrict__ w2,
                                               float* __restrict__ out) {
    const float* src = (STEP == 0 || STEP == 2) ? g_Z2a : g_Z2b;
    float* dst = (STEP == 1) ? g_Z2a : g_Z2b;
    int wid = (blockIdx.x * blockDim.x + threadIdx.x) >> 5;
    int lane = threadIdx.x & 31;
    if (wid >= NN) return;
    int beg = g_off[wid], end = g_off[wid + 1];
    float ax = 0.f, ay = 0.f, az = 0.f;
    for (int p = beg + lane; p < end; p += 32) {
        int2 ent = __ldg(&g_csr[p]);
        float w = __int_as_float(ent.y);
        float4 v = *(const float4*)(src + (size_t)ent.x * 4);
        ax += w * v.x; ay += w * v.y; az += w * v.z;
    }
#pragma unroll
    for (int o = 16; o; o >>= 1) {
        ax += __shfl_xor_sync(0xffffffffu, ax, o);
        ay += __shfl_xor_sync(0xffffffffu, ay, o);
        az += __shfl_xor_sync(0xffffffffu, az, o);
    }
    if (lane) return;
    float4 r = *(const float4*)(g_root2 + (size_t)wid * 4);
    if (STEP >= 1) {
        ax *= __ldg(w2 + 0); ay *= __ldg(w2 + 1); az *= __ldg(w2 + 2);
    }
    ax += r.x; ay += r.y; az += r.z;
    if (STEP == 3) {
        float s = (ax + ay + az) * (1.f / 3.f);
        out[wid] = 1.f / (1.f + expf(-s));
    } else {
        *(float4*)(dst + (size_t)wid * 4) = make_float4(ax, ay, az, 0.f);
    }
}

// ---------------- launch ---------------------------------------------------
extern "C" void kernel_launch(void* const* d_in, const int* in_sizes, int n_in,
                              void* d_out, int out_size) {
    const float* x     = (const float*)d_in[0];
    const int*   ei    = (const int*)d_in[1];
    const float* ew    = (const float*)d_in[2];
    const float* c1_iw = (const float*)d_in[3];
    const float* c1_w  = (const float*)d_in[4];
    const float* c1_rw = (const float*)d_in[5];
    const float* c1_b  = (const float*)d_in[6];
    const float* bn_g  = (const float*)d_in[7];
    const float* bn_b  = (const float*)d_in[8];
    const float* bn_m  = (const float*)d_in[9];
    const float* bn_v  = (const float*)d_in[10];
    const float* c2_iw = (const float*)d_in[11];
    const float* c2_w  = (const float*)d_in[12];
    const float* c2_rw = (const float*)d_in[13];
    const float* c2_b  = (const float*)d_in[14];
    float* out = (float*)d_out;

    const int* row = ei;
    const int* col = ei + EE;

    const int GN = (NN + 255) / 256;
    const int GE = (EE + 255) / 256;
    const int NB1 = (NN + 1023) / 1024;        // 98
    const int GW = (NN * 32 + 255) / 256;      // warp-per-node grids
    const int G48 = NN / 32;                   // 3125 (exact)
    const int GF = NN / 8;                     // 12500 (exact)

    // CSR build (by col), gcn_norm fused into scatter
    k_zero<<<GN, 256>>>();
    k_hist<<<GE, 256>>>(col, ew);
    k_dis<<<GN, 256>>>();
    k_scan1<<<NB1, 1024>>>();
    k_scan2<<<1, 32>>>(NB1);
    k_scan3<<<GN, 256>>>();
    k_scatter<<<GE, 256>>>(row, col, ew);

    // conv1: rank-1 first iteration + 3 fused gather/node iterations
    k_first<<<GF, 256>>>(x, c1_iw, c1_rw, c1_b);
    k_gath_fused<0><<<G48, 384>>>(x, c1_w, c1_rw, c1_b, bn_g, bn_b, bn_m, bn_v,
                                  c2_iw, c2_rw, c2_b);
    k_gath_fused<1><<<G48, 384>>>(x, c1_w, c1_rw, c1_b, bn_g, bn_b, bn_m, bn_v,
                                  c2_iw, c2_rw, c2_b);
    k_gath_fused<2><<<G48, 384>>>(x, c1_w, c1_rw, c1_b, bn_g, bn_b, bn_m, bn_v,
                                  c2_iw, c2_rw, c2_b);

    // conv2: 4 gather iterations, node updates fused into epilogue
    k_gath4<0><<<GW, 256>>>(c2_w, out);
    k_gath4<1><<<GW, 256>>>(c2_w, out);
    k_gath4<2><<<GW, 256>>>(c2_w, out);
    k_gath4<3><<<GW, 256>>>(c2_w, out);

    (void)in_sizes; (void)n_in; (void)out_size;
}

// round 8
// speedup vs baseline: 1.1552x; 1.1552x over previous
#include <cuda_runtime.h>
#include <cuda_fp16.h>

#define NN 100000
#define EE 3200000

// ---------------- scratch (device globals; never passed as kernel args) ----
__device__ __align__(16) int    g_cnt[NN];        // histogram, then scatter cursor
__device__ __align__(16) float  g_dis[NN];        // weighted degree, then deg^-1/2
__device__ __align__(16) int    g_off[NN + 1];    // CSR offsets (by col)
__device__ __align__(16) int    g_bsum[128];
__device__ __align__(16) int    g_bsum2[128];
__device__ __align__(16) int2   g_csr[EE];        // (row, norm-as-int) grouped by col
__device__ __align__(16) float  g_Lx[NN];         // Lx (rank-1 first iteration)
__device__ __align__(16) __half g_Ah[NN * 48];    // conv1 state (fp16, 9.6 MB)
__device__ __align__(16) float  g_Y[NN * 48];     // raw aggregate L*out_t (fp32)
__device__ __align__(16) float  g_Z2a[NN * 4];    // conv2 ping (K=3 padded to 4)
__device__ __align__(16) float  g_Z2b[NN * 4];    // conv2 pong
__device__ __align__(16) float  g_root2[NN * 4];

// pack 4 floats -> 4 halves (8 bytes)
__device__ __forceinline__ void st_half4(__half* p, float4 v) {
    union { __half2 h[2]; uint2 u; } pk;
    pk.h[0] = __floats2half2_rn(v.x, v.y);
    pk.h[1] = __floats2half2_rn(v.z, v.w);
    *(uint2*)p = pk.u;
}

__device__ __forceinline__ float4 ld_half4(const __half* p) {
    union { uint2 u; __half2 h[2]; } pk;
    pk.u = *(const uint2*)p;
    float2 f0 = __half22float2(pk.h[0]);
    float2 f1 = __half22float2(pk.h[1]);
    return make_float4(f0.x, f0.y, f1.x, f1.y);
}

// ---------------- CSR build ------------------------------------------------
__global__ void __launch_bounds__(256) k_zero() {
    int n = blockIdx.x * blockDim.x + threadIdx.x;
    if (n < NN) { g_cnt[n] = 0; g_dis[n] = 0.f; }
}

__global__ void __launch_bounds__(256) k_hist(const int* __restrict__ col,
                                              const float* __restrict__ ew) {
    int e = blockIdx.x * blockDim.x + threadIdx.x;
    if (e >= EE) return;
    int c = col[e];
    atomicAdd(&g_cnt[c], 1);
    atomicAdd(&g_dis[c], ew[e]);
}

// per-block scan of g_cnt; also finishes g_dis (deg -> rsqrt), fused to save a launch
__global__ void __launch_bounds__(1024) k_scan1() {
    __shared__ int s[1024];
    int i = blockIdx.x * 1024 + threadIdx.x;
    if (i < NN) {
        float d = g_dis[i];
        g_dis[i] = (d > 0.f) ? rsqrtf(fmaxf(d, 1e-12f)) : 0.f;
    }
    int v = (i < NN) ? g_cnt[i] : 0;
    s[threadIdx.x] = v;
    __syncthreads();
#pragma unroll
    for (int off = 1; off < 1024; off <<= 1) {
        int t = (threadIdx.x >= off) ? s[threadIdx.x - off] : 0;
        __syncthreads();
        s[threadIdx.x] += t;
        __syncthreads();
    }
    if (i < NN) g_off[i] = s[threadIdx.x] - v;
    if (threadIdx.x == 1023) g_bsum[blockIdx.x] = s[1023];
}

__global__ void __launch_bounds__(32) k_scan2(int nb) {
    if (threadIdx.x == 0 && blockIdx.x == 0) {
        int acc = 0;
        for (int b = 0; b < nb; b++) { g_bsum2[b] = acc; acc += g_bsum[b]; }
    }
}

__global__ void __launch_bounds__(256) k_scan3() {
    int i = blockIdx.x * blockDim.x + threadIdx.x;
    if (i < NN) {
        int v = g_off[i] + g_bsum2[i >> 10];
        g_off[i] = v;
        g_cnt[i] = v;
    }
    if (i == 0) g_off[NN] = EE;
}

__global__ void __launch_bounds__(256) k_scatter(const int* __restrict__ row,
                                                 const int* __restrict__ col,
                                                 const float* __restrict__ ew) {
    int e = blockIdx.x * blockDim.x + threadIdx.x;
    if (e >= EE) return;
    int r = row[e], c = col[e];
    float nm = g_dis[r] * ew[e] * g_dis[c];
    int p = atomicAdd(&g_cnt[c], 1);
    g_csr[p] = make_int2(r, __float_as_int(nm));
}

// ---------------- conv1 first iteration (rank-1): warp per node ------------
// s1 = (Lx)[n]; out_1 = relu(s1*iw + x*rw + b) -> g_Ah (fp16)
__global__ void __launch_bounds__(256) k_first(const float* __restrict__ x,
                                               const float* __restrict__ iw,
                                               const float* __restrict__ rw,
                                               const float* __restrict__ bias) {
    __shared__ float siw[48], srw[48], sb[48];
    if (threadIdx.x < 48) {
        siw[threadIdx.x] = iw[threadIdx.x];
        srw[threadIdx.x] = rw[threadIdx.x];
        sb[threadIdx.x]  = bias[threadIdx.x];
    }
    __syncthreads();
    int n = blockIdx.x * 8 + (threadIdx.x >> 5);   // 12500*8 = 100000 exact
    int lane = threadIdx.x & 31;
    int beg = g_off[n], end = g_off[n + 1];
    float acc = 0.f;
    for (int p = beg + lane; p < end; p += 32) {
        int2 ent = __ldg(&g_csr[p]);
        acc += __int_as_float(ent.y) * __ldg(x + ent.x);
    }
#pragma unroll
    for (int o = 16; o; o >>= 1) acc += __shfl_xor_sync(0xffffffffu, acc, o);
    float s1 = __shfl_sync(0xffffffffu, acc, 0);
    if (lane < 12) {
        float s0 = __ldg(x + n);
        int i = lane * 4;
        float4 a;
        a.x = fmaxf(s1 * siw[i+0] + s0 * srw[i+0] + sb[i+0], 0.f);
        a.y = fmaxf(s1 * siw[i+1] + s0 * srw[i+1] + sb[i+1], 0.f);
        a.z = fmaxf(s1 * siw[i+2] + s0 * srw[i+2] + sb[i+2], 0.f);
        a.w = fmaxf(s1 * siw[i+3] + s0 * srw[i+3] + sb[i+3], 0.f);
        st_half4(g_Ah + (size_t)n * 48 + i, a);
    }
}

// ---------------- conv1 heavy gather: g_Y[n] = sum norm * g_Ah[row] --------
// 12-thread groups, 32 nodes per 384-thread block (3125*32 = 100000 exact).
// fp16 source (8B per thread per edge), fp32 accumulate. No smem, tiny regs.
__global__ void __launch_bounds__(384) k_gath48() {
    int gid = threadIdx.x / 12;
    int l4 = (threadIdx.x - gid * 12) * 4;
    int n = blockIdx.x * 32 + gid;
    int beg = g_off[n], end = g_off[n + 1];
    float4 acc = make_float4(0.f, 0.f, 0.f, 0.f);
    for (int p = beg; p < end; ++p) {
        int2 ent = __ldg(&g_csr[p]);
        float w = __int_as_float(ent.y);
        float4 v = ld_half4(g_Ah + (size_t)ent.x * 48 + l4);
        acc.x += w * v.x; acc.y += w * v.y; acc.z += w * v.z; acc.w += w * v.w;
    }
    *(float4*)(g_Y + (size_t)n * 48 + l4) = acc;
}

// ---------------- conv1 node update (mid): Ah = relu(Y@W + x*rw + b) -------
__global__ void __launch_bounds__(256) k_node_mid(const float* __restrict__ x,
                                                  const float* __restrict__ W,
                                                  const float* __restrict__ rw,
                                                  const float* __restrict__ bias) {
    __shared__ float sW[768], srw[48], sb[48];
    for (int i = threadIdx.x; i < 768; i += blockDim.x) sW[i] = W[i];
    if (threadIdx.x < 48) {
        srw[threadIdx.x] = rw[threadIdx.x];
        sb[threadIdx.x]  = bias[threadIdx.x];
    }
    __syncthreads();
    int n = blockIdx.x * blockDim.x + threadIdx.x;
    if (n >= NN) return;
    float xv = x[n];
    const float* Y = g_Y + (size_t)n * 48;
    __half* A = g_Ah + (size_t)n * 48;
#pragma unroll
    for (int k = 0; k < 3; k++) {
        float y[16];
#pragma unroll
        for (int q = 0; q < 16; q++) y[q] = Y[k * 16 + q];
#pragma unroll
        for (int p = 0; p < 16; p += 4) {
            float4 o;
            o.x = xv * srw[k*16 + p + 0] + sb[k*16 + p + 0];
            o.y = xv * srw[k*16 + p + 1] + sb[k*16 + p + 1];
            o.z = xv * srw[k*16 + p + 2] + sb[k*16 + p + 2];
            o.w = xv * srw[k*16 + p + 3] + sb[k*16 + p + 3];
#pragma unroll
            for (int q = 0; q < 16; q++) {
                float yv = y[q];
                const float* wq = &sW[k * 256 + q * 16 + p];
                o.x += yv * wq[0];
                o.y += yv * wq[1];
                o.z += yv * wq[2];
                o.w += yv * wq[3];
            }
            o.x = fmaxf(o.x, 0.f); o.y = fmaxf(o.y, 0.f);
            o.z = fmaxf(o.z, 0.f); o.w = fmaxf(o.w, 0.f);
            st_half4(A + k * 16 + p, o);
        }
    }
}

// ---------------- conv1 final node update + BN + ReLU + conv2 init ---------
__global__ void __launch_bounds__(256) k_node_last(
    const float* __restrict__ x, const float* __restrict__ W,
    const float* __restrict__ rw, const float* __restrict__ bias,
    const float* __restrict__ gamma, const float* __restrict__ beta,
    const float* __restrict__ mean,  const float* __restrict__ var,
    const float* __restrict__ iw2,   const float* __restrict__ rw2,
    const float* __restrict__ b2) {
    __shared__ float sW[768], srw[48], sb[48];
    __shared__ float sscale[16], sshift[16], siw2[48], srw2[48], sb2[3];
    for (int i = threadIdx.x; i < 768; i += blockDim.x) sW[i] = W[i];
    if (threadIdx.x < 48) {
        srw[threadIdx.x] = rw[threadIdx.x];
        sb[threadIdx.x]  = bias[threadIdx.x];
    }
    if (threadIdx.x >= 64 && threadIdx.x < 80) {
        int f = threadIdx.x - 64;
        float sc = gamma[f] * rsqrtf(var[f] + 1e-5f);
        sscale[f] = sc;
        sshift[f] = beta[f] - mean[f] * sc;
    }
    if (threadIdx.x >= 96 && threadIdx.x < 144) {
        siw2[threadIdx.x - 96] = iw2[threadIdx.x - 96];
        srw2[threadIdx.x - 96] = rw2[threadIdx.x - 96];
    }
    if (threadIdx.x >= 160 && threadIdx.x < 163) sb2[threadIdx.x - 160] = b2[threadIdx.x - 160];
    __syncthreads();
    int n = blockIdx.x * blockDim.x + threadIdx.x;
    if (n >= NN) return;
    float xv = x[n];
    const float* Y = g_Y + (size_t)n * 48;
    float h[16];
#pragma unroll
    for (int f = 0; f < 16; f++) h[f] = 0.f;
#pragma unroll
    for (int k = 0; k < 3; k++) {
        float y[16];
#pragma unroll
        for (int q = 0; q < 16; q++) y[q] = Y[k * 16 + q];
#pragma unroll
        for (int p = 0; p < 16; p++) {
            float o = xv * srw[k * 16 + p] + sb[k * 16 + p];
#pragma unroll
            for (int q = 0; q < 16; q++) o += y[q] * sW[k * 256 + q * 16 + p];
            h[p] += fmaxf(o, 0.f);
        }
    }
#pragma unroll
    for (int f = 0; f < 16; f++) {
        float a = h[f] * (1.f / 3.f) * sscale[f] + sshift[f];
        h[f] = fmaxf(a, 0.f);
    }
    float z[3], r2[3];
#pragma unroll
    for (int k = 0; k < 3; k++) {
        float za = 0.f, ra = 0.f;
#pragma unroll
        for (int f = 0; f < 16; f++) {
            za += h[f] * siw2[k * 16 + f];
            ra += h[f] * srw2[k * 16 + f];
        }
        z[k] = za;
        r2[k] = ra + sb2[k];
    }
    *(float4*)(g_Z2a + (size_t)n * 4)   = make_float4(z[0], z[1], z[2], 0.f);
    *(float4*)(g_root2 + (size_t)n * 4) = make_float4(r2[0], r2[1], r2[2], 0.f);
}

// ---------------- conv2 gather + fused node update -------------------------
// STEP 0: Z2b = L Z2a + root2
// STEP 1: Z2a = w * (L Z2b) + root2
// STEP 2: Z2b = w * (L Z2a) + root2
// STEP 3: out = sigmoid(mean(w * (L Z2b) + root2))
template <int STEP>
__global__ void __launch_bounds__(256) k_gath4(const float* __restrict__ w2,
                                               float* __restrict__ out) {
    const float* src = (STEP == 0 || STEP == 2) ? g_Z2a : g_Z2b;
    float* dst = (STEP == 1) ? g_Z2a : g_Z2b;
    int wid = (blockIdx.x * blockDim.x + threadIdx.x) >> 5;
    int lane = threadIdx.x & 31;
    if (wid >= NN) return;
    int beg = g_off[wid], end = g_off[wid + 1];
    float ax = 0.f, ay = 0.f, az = 0.f;
    for (int p = beg + lane; p < end; p += 32) {
        int2 ent = __ldg(&g_csr[p]);
        float w = __int_as_float(ent.y);
        float4 v = *(const float4*)(src + (size_t)ent.x * 4);
        ax += w * v.x; ay += w * v.y; az += w * v.z;
    }
#pragma unroll
    for (int o = 16; o; o >>= 1) {
        ax += __shfl_xor_sync(0xffffffffu, ax, o);
        ay += __shfl_xor_sync(0xffffffffu, ay, o);
        az += __shfl_xor_sync(0xffffffffu, az, o);
    }
    if (lane) return;
    float4 r = *(const float4*)(g_root2 + (size_t)wid * 4);
    if (STEP >= 1) {
        ax *= __ldg(w2 + 0); ay *= __ldg(w2 + 1); az *= __ldg(w2 + 2);
    }
    ax += r.x; ay += r.y; az += r.z;
    if (STEP == 3) {
        float s = (ax + ay + az) * (1.f / 3.f);
        out[wid] = 1.f / (1.f + expf(-s));
    } else {
        *(float4*)(dst + (size_t)wid * 4) = make_float4(ax, ay, az, 0.f);
    }
}

// ---------------- launch ---------------------------------------------------
extern "C" void kernel_launch(void* const* d_in, const int* in_sizes, int n_in,
                              void* d_out, int out_size) {
    const float* x     = (const float*)d_in[0];
    const int*   ei    = (const int*)d_in[1];
    const float* ew    = (const float*)d_in[2];
    const float* c1_iw = (const float*)d_in[3];
    const float* c1_w  = (const float*)d_in[4];
    const float* c1_rw = (const float*)d_in[5];
    const float* c1_b  = (const float*)d_in[6];
    const float* bn_g  = (const float*)d_in[7];
    const float* bn_b  = (const float*)d_in[8];
    const float* bn_m  = (const float*)d_in[9];
    const float* bn_v  = (const float*)d_in[10];
    const float* c2_iw = (const float*)d_in[11];
    const float* c2_w  = (const float*)d_in[12];
    const float* c2_rw = (const float*)d_in[13];
    const float* c2_b  = (const float*)d_in[14];
    float* out = (float*)d_out;

    const int* row = ei;
    const int* col = ei + EE;

    const int GN = (NN + 255) / 256;
    const int GE = (EE + 255) / 256;
    const int NB1 = (NN + 1023) / 1024;        // 98
    const int GW = (NN * 32 + 255) / 256;      // warp-per-node grids
    const int G48 = NN / 32;                   // 3125 (exact)
    const int GF = NN / 8;                     // 12500 (exact)

    // CSR build (by col), gcn_norm fused into scatter
    k_zero<<<GN, 256>>>();
    k_hist<<<GE, 256>>>(col, ew);
    k_scan1<<<NB1, 1024>>>();                  // scan + deg->rsqrt fused
    k_scan2<<<1, 32>>>(NB1);
    k_scan3<<<GN, 256>>>();
    k_scatter<<<GE, 256>>>(row, col, ew);

    // conv1: rank-1 first iteration, then 3 gather+node iterations (fp16 state)
    k_first<<<GF, 256>>>(x, c1_iw, c1_rw, c1_b);
    for (int t = 0; t < 3; t++) {
        k_gath48<<<G48, 384>>>();
        if (t < 2)
            k_node_mid<<<GN, 256>>>(x, c1_w, c1_rw, c1_b);
        else
            k_node_last<<<GN, 256>>>(x, c1_w, c1_rw, c1_b, bn_g, bn_b, bn_m, bn_v,
                                     c2_iw, c2_rw, c2_b);
    }

    // conv2: 4 gather iterations, node updates fused into epilogue
    k_gath4<0><<<GW, 256>>>(c2_w, out);
    k_gath4<1><<<GW, 256>>>(c2_w, out);
    k_gath4<2><<<GW, 256>>>(c2_w, out);
    k_gath4<3><<<GW, 256>>>(c2_w, out);

    (void)in_sizes; (void)n_in; (void)out_size;
}

// round 9
// speedup vs baseline: 1.1588x; 1.0031x over previous
#include <cuda_runtime.h>
#include <cuda_fp16.h>

#define NN 100000
#define EE 3200000

// ---------------- scratch (device globals; never passed as kernel args) ----
__device__ __align__(16) int    g_cnt[NN];        // histogram, then scatter cursor
__device__ __align__(16) float  g_dis[NN];        // weighted degree, then deg^-1/2
__device__ __align__(16) int    g_off[NN + 1];    // CSR offsets (by col)
__device__ __align__(16) int    g_bsum[128];
__device__ __align__(16) int    g_bsum2[128];
__device__ __align__(16) int2   g_csr[EE];        // (row, norm-as-int) grouped by col
__device__ __align__(16) float  g_Lx[NN];         // Lx (rank-1 first iteration)
__device__ __align__(16) __half g_Ah[NN * 48];    // conv1 state (fp16, 9.6 MB)
__device__ __align__(16) float  g_Y[NN * 48];     // raw aggregate L*out_t (fp32)
__device__ __align__(16) float  g_Z2a[NN * 4];    // conv2 ping (K=3 padded to 4)
__device__ __align__(16) float  g_Z2b[NN * 4];    // conv2 pong
__device__ __align__(16) float  g_root2[NN * 4];

// pack 4 floats -> 4 halves (8 bytes)
__device__ __forceinline__ void st_half4(__half* p, float4 v) {
    union { __half2 h[2]; uint2 u; } pk;
    pk.h[0] = __floats2half2_rn(v.x, v.y);
    pk.h[1] = __floats2half2_rn(v.z, v.w);
    *(uint2*)p = pk.u;
}

__device__ __forceinline__ float4 ld_half4(const __half* p) {
    union { uint2 u; __half2 h[2]; } pk;
    pk.u = *(const uint2*)p;
    float2 f0 = __half22float2(pk.h[0]);
    float2 f1 = __half22float2(pk.h[1]);
    return make_float4(f0.x, f0.y, f1.x, f1.y);
}

// ---------------- CSR build ------------------------------------------------
__global__ void __launch_bounds__(256) k_zero() {
    int n = blockIdx.x * blockDim.x + threadIdx.x;
    if (n < NN) { g_cnt[n] = 0; g_dis[n] = 0.f; }
}

__global__ void __launch_bounds__(256) k_hist(const int* __restrict__ col,
                                              const float* __restrict__ ew) {
    int e = blockIdx.x * blockDim.x + threadIdx.x;
    if (e >= EE) return;
    int c = col[e];
    atomicAdd(&g_cnt[c], 1);
    atomicAdd(&g_dis[c], ew[e]);
}

// per-block scan of g_cnt; also finishes g_dis (deg -> rsqrt), fused to save a launch
__global__ void __launch_bounds__(1024) k_scan1() {
    __shared__ int s[1024];
    int i = blockIdx.x * 1024 + threadIdx.x;
    if (i < NN) {
        float d = g_dis[i];
        g_dis[i] = (d > 0.f) ? rsqrtf(fmaxf(d, 1e-12f)) : 0.f;
    }
    int v = (i < NN) ? g_cnt[i] : 0;
    s[threadIdx.x] = v;
    __syncthreads();
#pragma unroll
    for (int off = 1; off < 1024; off <<= 1) {
        int t = (threadIdx.x >= off) ? s[threadIdx.x - off] : 0;
        __syncthreads();
        s[threadIdx.x] += t;
        __syncthreads();
    }
    if (i < NN) g_off[i] = s[threadIdx.x] - v;
    if (threadIdx.x == 1023) g_bsum[blockIdx.x] = s[1023];
}

__global__ void __launch_bounds__(32) k_scan2(int nb) {
    if (threadIdx.x == 0 && blockIdx.x == 0) {
        int acc = 0;
        for (int b = 0; b < nb; b++) { g_bsum2[b] = acc; acc += g_bsum[b]; }
    }
}

__global__ void __launch_bounds__(256) k_scan3() {
    int i = blockIdx.x * blockDim.x + threadIdx.x;
    if (i < NN) {
        int v = g_off[i] + g_bsum2[i >> 10];
        g_off[i] = v;
        g_cnt[i] = v;
    }
    if (i == 0) g_off[NN] = EE;
}

__global__ void __launch_bounds__(256) k_scatter(const int* __restrict__ row,
                                                 const int* __restrict__ col,
                                                 const float* __restrict__ ew) {
    int e = blockIdx.x * blockDim.x + threadIdx.x;
    if (e >= EE) return;
    int r = row[e], c = col[e];
    float nm = g_dis[r] * ew[e] * g_dis[c];
    int p = atomicAdd(&g_cnt[c], 1);
    g_csr[p] = make_int2(r, __float_as_int(nm));
}

// ---------------- conv1 first iteration (rank-1): warp per node ------------
// s1 = (Lx)[n]; out_1 = relu(s1*iw + x*rw + b) -> g_Ah (fp16)
__global__ void __launch_bounds__(256) k_first(const float* __restrict__ x,
                                               const float* __restrict__ iw,
                                               const float* __restrict__ rw,
                                               const float* __restrict__ bias) {
    __shared__ float siw[48], srw[48], sb[48];
    if (threadIdx.x < 48) {
        siw[threadIdx.x] = iw[threadIdx.x];
        srw[threadIdx.x] = rw[threadIdx.x];
        sb[threadIdx.x]  = bias[threadIdx.x];
    }
    __syncthreads();
    int n = blockIdx.x * 8 + (threadIdx.x >> 5);   // 12500*8 = 100000 exact
    int lane = threadIdx.x & 31;
    int beg = g_off[n], end = g_off[n + 1];
    float acc = 0.f;
    for (int p = beg + lane; p < end; p += 32) {
        int2 ent = __ldg(&g_csr[p]);
        acc += __int_as_float(ent.y) * __ldg(x + ent.x);
    }
#pragma unroll
    for (int o = 16; o; o >>= 1) acc += __shfl_xor_sync(0xffffffffu, acc, o);
    float s1 = __shfl_sync(0xffffffffu, acc, 0);
    if (lane < 12) {
        float s0 = __ldg(x + n);
        int i = lane * 4;
        float4 a;
        a.x = fmaxf(s1 * siw[i+0] + s0 * srw[i+0] + sb[i+0], 0.f);
        a.y = fmaxf(s1 * siw[i+1] + s0 * srw[i+1] + sb[i+1], 0.f);
        a.z = fmaxf(s1 * siw[i+2] + s0 * srw[i+2] + sb[i+2], 0.f);
        a.w = fmaxf(s1 * siw[i+3] + s0 * srw[i+3] + sb[i+3], 0.f);
        st_half4(g_Ah + (size_t)n * 48 + i, a);
    }
}

// ---------------- conv1 heavy gather: g_Y[n] = sum norm * g_Ah[row] --------
// 12-thread groups, 32 nodes per 384-thread block (3125*32 = 100000 exact).
// fp16 source (8B per thread per edge), fp32 accumulate. No smem, tiny regs.
__global__ void __launch_bounds__(384) k_gath48() {
    int gid = threadIdx.x / 12;
    int l4 = (threadIdx.x - gid * 12) * 4;
    int n = blockIdx.x * 32 + gid;
    int beg = g_off[n], end = g_off[n + 1];
    float4 acc = make_float4(0.f, 0.f, 0.f, 0.f);
    for (int p = beg; p < end; ++p) {
        int2 ent = __ldg(&g_csr[p]);
        float w = __int_as_float(ent.y);
        float4 v = ld_half4(g_Ah + (size_t)ent.x * 48 + l4);
        acc.x += w * v.x; acc.y += w * v.y; acc.z += w * v.z; acc.w += w * v.w;
    }
    *(float4*)(g_Y + (size_t)n * 48 + l4) = acc;
}

// ---------------- conv1 node update (mid): Ah = relu(Y@W + x*rw + b) -------
__global__ void __launch_bounds__(256) k_node_mid(const float* __restrict__ x,
                                                  const float* __restrict__ W,
                                                  const float* __restrict__ rw,
                                                  const float* __restrict__ bias) {
    __shared__ float sW[768], srw[48], sb[48];
    for (int i = threadIdx.x; i < 768; i += blockDim.x) sW[i] = W[i];
    if (threadIdx.x < 48) {
        srw[threadIdx.x] = rw[threadIdx.x];
        sb[threadIdx.x]  = bias[threadIdx.x];
    }
    __syncthreads();
    int n = blockIdx.x * blockDim.x + threadIdx.x;
    if (n >= NN) return;
    float xv = x[n];
    const float* Y = g_Y + (size_t)n * 48;
    __half* A = g_Ah + (size_t)n * 48;
#pragma unroll
    for (int k = 0; k < 3; k++) {
        float y[16];
#pragma unroll
        for (int q = 0; q < 16; q++) y[q] = Y[k * 16 + q];
#pragma unroll
        for (int p = 0; p < 16; p += 4) {
            float4 o;
            o.x = xv * srw[k*16 + p + 0] + sb[k*16 + p + 0];
            o.y = xv * srw[k*16 + p + 1] + sb[k*16 + p + 1];
            o.z = xv * srw[k*16 + p + 2] + sb[k*16 + p + 2];
            o.w = xv * srw[k*16 + p + 3] + sb[k*16 + p + 3];
#pragma unroll
            for (int q = 0; q < 16; q++) {
                float yv = y[q];
                const float* wq = &sW[k * 256 + q * 16 + p];
                o.x += yv * wq[0];
                o.y += yv * wq[1];
                o.z += yv * wq[2];
                o.w += yv * wq[3];
            }
            o.x = fmaxf(o.x, 0.f); o.y = fmaxf(o.y, 0.f);
            o.z = fmaxf(o.z, 0.f); o.w = fmaxf(o.w, 0.f);
            st_half4(A + k * 16 + p, o);
        }
    }
}

// ---------------- conv1 final node update + BN + ReLU + conv2 init ---------
__global__ void __launch_bounds__(256) k_node_last(
    const float* __restrict__ x, const float* __restrict__ W,
    const float* __restrict__ rw, const float* __restrict__ bias,
    const float* __restrict__ gamma, const float* __restrict__ beta,
    const float* __restrict__ mean,  const float* __restrict__ var,
    const float* __restrict__ iw2,   const float* __restrict__ rw2,
    const float* __restrict__ b2) {
    __shared__ float sW[768], srw[48], sb[48];
    __shared__ float sscale[16], sshift[16], siw2[48], srw2[48], sb2[3];
    for (int i = threadIdx.x; i < 768; i += blockDim.x) sW[i] = W[i];
    if (threadIdx.x < 48) {
        srw[threadIdx.x] = rw[threadIdx.x];
        sb[threadIdx.x]  = bias[threadIdx.x];
    }
    if (threadIdx.x >= 64 && threadIdx.x < 80) {
        int f = threadIdx.x - 64;
        float sc = gamma[f] * rsqrtf(var[f] + 1e-5f);
        sscale[f] = sc;
        sshift[f] = beta[f] - mean[f] * sc;
    }
    if (threadIdx.x >= 96 && threadIdx.x < 144) {
        siw2[threadIdx.x - 96] = iw2[threadIdx.x - 96];
        srw2[threadIdx.x - 96] = rw2[threadIdx.x - 96];
    }
    if (threadIdx.x >= 160 && threadIdx.x < 163) sb2[threadIdx.x - 160] = b2[threadIdx.x - 160];
    __syncthreads();
    int n = blockIdx.x * blockDim.x + threadIdx.x;
    if (n >= NN) return;
    float xv = x[n];
    const float* Y = g_Y + (size_t)n * 48;
    float h[16];
#pragma unroll
    for (int f = 0; f < 16; f++) h[f] = 0.f;
#pragma unroll
    for (int k = 0; k < 3; k++) {
        float y[16];
#pragma unroll
        for (int q = 0; q < 16; q++) y[q] = Y[k * 16 + q];
#pragma unroll
        for (int p = 0; p < 16; p++) {
            float o = xv * srw[k * 16 + p] + sb[k * 16 + p];
#pragma unroll
            for (int q = 0; q < 16; q++) o += y[q] * sW[k * 256 + q * 16 + p];
            h[p] += fmaxf(o, 0.f);
        }
    }
#pragma unroll
    for (int f = 0; f < 16; f++) {
        float a = h[f] * (1.f / 3.f) * sscale[f] + sshift[f];
        h[f] = fmaxf(a, 0.f);
    }
    float z[3], r2[3];
#pragma unroll
    for (int k = 0; k < 3; k++) {
        float za = 0.f, ra = 0.f;
#pragma unroll
        for (int f = 0; f < 16; f++) {
            za += h[f] * siw2[k * 16 + f];
            ra += h[f] * srw2[k * 16 + f];
        }
        z[k] = za;
        r2[k] = ra + sb2[k];
    }
    *(float4*)(g_Z2a + (size_t)n * 4)   = make_float4(z[0], z[1], z[2], 0.f);
    *(float4*)(g_root2 + (size_t)n * 4) = make_float4(r2[0], r2[1], r2[2], 0.f);
}

// ---------------- conv2 gather + fused node update -------------------------
// STEP 0: Z2b = L Z2a + root2
// STEP 1: Z2a = w * (L Z2b) + root2
// STEP 2: Z2b = w * (L Z2a) + root2
// STEP 3: out = sigmoid(mean(w * (L Z2b) + root2))
template <int STEP>
__global__ void __launch_bounds__(256) k_gath4(const float* __restrict__ w2,
                                               float* __restrict__ out) {
    const float* src = (STEP == 0 || STEP == 2) ? g_Z2a : g_Z2b;
    float* dst = (STEP == 1) ? g_Z2a : g_Z2b;
    int wid = (blockIdx.x * blockDim.x + threadIdx.x) >> 5;
    int lane = threadIdx.x & 31;
    if (wid >= NN) return;
    int beg = g_off[wid], end = g_off[wid + 1];
    float ax = 0.f, ay = 0.f, az = 0.f;
    for (int p = beg + lane; p < end; p += 32) {
        int2 ent = __ldg(&g_csr[p]);
        float w = __int_as_float(ent.y);
        float4 v = *(const float4*)(src + (size_t)ent.x * 4);
        ax += w * v.x; ay += w * v.y; az += w * v.z;
    }
#pragma unroll
    for (int o = 16; o; o >>= 1) {
        ax += __shfl_xor_sync(0xffffffffu, ax, o);
        ay += __shfl_xor_sync(0xffffffffu, ay, o);
        az += __shfl_xor_sync(0xffffffffu, az, o);
    }
    if (lane) return;
    float4 r = *(const float4*)(g_root2 + (size_t)wid * 4);
    if (STEP >= 1) {
        ax *= __ldg(w2 + 0); ay *= __ldg(w2 + 1); az *= __ldg(w2 + 2);
    }
    ax += r.x; ay += r.y; az += r.z;
    if (STEP == 3) {
        float s = (ax + ay + az) * (1.f / 3.f);
        out[wid] = 1.f / (1.f + expf(-s));
    } else {
        *(float4*)(dst + (size_t)wid * 4) = make_float4(ax, ay, az, 0.f);
    }
}

// ---------------- launch ---------------------------------------------------
extern "C" void kernel_launch(void* const* d_in, const int* in_sizes, int n_in,
                              void* d_out, int out_size) {
    const float* x     = (const float*)d_in[0];
    const int*   ei    = (const int*)d_in[1];
    const float* ew    = (const float*)d_in[2];
    const float* c1_iw = (const float*)d_in[3];
    const float* c1_w  = (const float*)d_in[4];
    const float* c1_rw = (const float*)d_in[5];
    const float* c1_b  = (const float*)d_in[6];
    const float* bn_g  = (const float*)d_in[7];
    const float* bn_b  = (const float*)d_in[8];
    const float* bn_m  = (const float*)d_in[9];
    const float* bn_v  = (const float*)d_in[10];
    const float* c2_iw = (const float*)d_in[11];
    const float* c2_w  = (const float*)d_in[12];
    const float* c2_rw = (const float*)d_in[13];
    const float* c2_b  = (const float*)d_in[14];
    float* out = (float*)d_out;

    const int* row = ei;
    const int* col = ei + EE;

    const int GN = (NN + 255) / 256;
    const int GE = (EE + 255) / 256;
    const int NB1 = (NN + 1023) / 1024;        // 98
    const int GW = (NN * 32 + 255) / 256;      // warp-per-node grids
    const int G48 = NN / 32;                   // 3125 (exact)
    const int GF = NN / 8;                     // 12500 (exact)

    // CSR build (by col), gcn_norm fused into scatter
    k_zero<<<GN, 256>>>();
    k_hist<<<GE, 256>>>(col, ew);
    k_scan1<<<NB1, 1024>>>();                  // scan + deg->rsqrt fused
    k_scan2<<<1, 32>>>(NB1);
    k_scan3<<<GN, 256>>>();
    k_scatter<<<GE, 256>>>(row, col, ew);

    // conv1: rank-1 first iteration, then 3 gather+node iterations (fp16 state)
    k_first<<<GF, 256>>>(x, c1_iw, c1_rw, c1_b);
    for (int t = 0; t < 3; t++) {
        k_gath48<<<G48, 384>>>();
        if (t < 2)
            k_node_mid<<<GN, 256>>>(x, c1_w, c1_rw, c1_b);
        else
            k_node_last<<<GN, 256>>>(x, c1_w, c1_rw, c1_b, bn_g, bn_b, bn_m, bn_v,
                                     c2_iw, c2_rw, c2_b);
    }

    // conv2: 4 gather iterations, node updates fused into epilogue
    k_gath4<0><<<GW, 256>>>(c2_w, out);
    k_gath4<1><<<GW, 256>>>(c2_w, out);
    k_gath4<2><<<GW, 256>>>(c2_w, out);
    k_gath4<3><<<GW, 256>>>(c2_w, out);

    (void)in_sizes; (void)n_in; (void)out_size;
}